// round 7
// baseline (speedup 1.0000x reference)
#include <cuda_runtime.h>
#include <math.h>

// Problem constants (fixed by the dataset)
#define BB   32
#define TT   2048
#define DD   1024
#define AA   1024
#define MTOT (BB * TT)   // 65536 rows of the big GEMM

// ---------------------------------------------------------------------------
// Scratch (static __device__ arrays: allocation-free, graph-capture safe)
// ---------------------------------------------------------------------------
__device__ float g_ws[BB * AA];        // W_a_s : [B, A]
__device__ float g_part[8 * MTOT];     // per-(n-block) score partials, deterministic
__device__ float g_esc[MTOT];          // exp(scores)
__device__ float g_invden[BB];         // 1 / sum_t exp(scores)

// ---------------------------------------------------------------------------
// Packed fp32x2 helpers (Blackwell FFMA2 — only reachable via PTX)
// ---------------------------------------------------------------------------
__device__ __forceinline__ unsigned long long pk2(float lo, float hi) {
    unsigned long long r;
    asm("mov.b64 %0, {%1, %2};" : "=l"(r) : "f"(lo), "f"(hi));
    return r;
}
__device__ __forceinline__ void up2(unsigned long long v, float& lo, float& hi) {
    asm("mov.b64 {%0, %1}, %2;" : "=f"(lo), "=f"(hi) : "l"(v));
}
__device__ __forceinline__ void fma2(unsigned long long& d,
                                     unsigned long long a,
                                     unsigned long long b) {
    asm("fma.rn.f32x2 %0, %1, %2, %3;" : "=l"(d) : "l"(a), "l"(b), "l"(d));
}

// ---------------------------------------------------------------------------
// Kernel 0: g_ws[b][a] = sum_d s[b][d] * W_a[d][a]   (tiny GEMM, 67 MFLOP)
// grid (8, 32), block 128
// ---------------------------------------------------------------------------
__global__ void ws_kernel(const float* __restrict__ s, const float* __restrict__ W) {
    __shared__ float ss[DD];
    const int b = blockIdx.y;
    const int a = blockIdx.x * 128 + threadIdx.x;

    for (int i = threadIdx.x; i < DD; i += 128) ss[i] = s[b * DD + i];
    __syncthreads();

    float a0 = 0.f, a1 = 0.f, a2 = 0.f, a3 = 0.f;
    for (int d = 0; d < DD; d += 4) {
        a0 += ss[d + 0] * W[(size_t)(d + 0) * AA + a];
        a1 += ss[d + 1] * W[(size_t)(d + 1) * AA + a];
        a2 += ss[d + 2] * W[(size_t)(d + 2) * AA + a];
        a3 += ss[d + 3] * W[(size_t)(d + 3) * AA + a];
    }
    g_ws[b * AA + a] = (a0 + a1) + (a2 + a3);
}

// ---------------------------------------------------------------------------
// Kernel 1: fused GEMM + tanh + dot(v) -> per-n-block score partials.
//
// Tile: BM=128 x BN=128 x BK=16, 256 threads, 8x8 micro-tile per thread,
// accumulated in f32x2 pairs via fma.rn.f32x2 (2 FMAs per issue slot).
// Each block owns rows [m0, m0+128) (all inside one batch b since 128 | T)
// and columns [n0, n0+128). After the K loop it collapses its tile through
// tanh(acc + ws)·v into one partial per row and writes g_part[nb][m]
// (exactly one writer per slot -> deterministic, no atomics, no zero-init).
//
// grid (8, 512), block 256
// ---------------------------------------------------------------------------
__global__ void __launch_bounds__(256, 2)
score_gemm_kernel(const float* __restrict__ h,
                  const float* __restrict__ U,
                  const float* __restrict__ v) {
    __shared__ __align__(16) float As[16][132];   // [k][m], padded: STS 2-way max
    __shared__ __align__(16) float Bs[16][128];   // [k][n]

    const int tid = threadIdx.x;
    const int nb  = blockIdx.x;          // 0..7
    const int n0  = nb * 128;
    const int m0  = blockIdx.y * 128;

    // global->shared load mapping
    const int arow = tid >> 2;           // 0..63
    const int acol = (tid & 3) << 2;     // 0,4,8,12
    const int brow = tid >> 5;           // 0..7
    const int bcol = (tid & 31) << 2;    // 0..124

    // compute mapping: 16x16 thread grid, 8x8 micro-tile (4+4 split)
    const int ty = tid >> 4;             // 0..15 -> M
    const int tx = tid & 15;             // 0..15 -> N

    const float* hA = h + (size_t)m0 * DD;

    unsigned long long acc[8][4];
#pragma unroll
    for (int i = 0; i < 8; i++)
#pragma unroll
        for (int j = 0; j < 4; j++) acc[i][j] = 0ull;

    for (int kt = 0; kt < DD; kt += 16) {
        // issue global loads first (latency overlapped with prior compute)
        float4 av0 = *reinterpret_cast<const float4*>(&hA[(size_t)arow        * DD + kt + acol]);
        float4 av1 = *reinterpret_cast<const float4*>(&hA[(size_t)(arow + 64) * DD + kt + acol]);
        float4 bv0 = *reinterpret_cast<const float4*>(&U[(size_t)(kt + brow)     * AA + n0 + bcol]);
        float4 bv1 = *reinterpret_cast<const float4*>(&U[(size_t)(kt + brow + 8) * AA + n0 + bcol]);

        __syncthreads();   // previous tile fully consumed
        As[acol + 0][arow] = av0.x;  As[acol + 1][arow] = av0.y;
        As[acol + 2][arow] = av0.z;  As[acol + 3][arow] = av0.w;
        As[acol + 0][arow + 64] = av1.x;  As[acol + 1][arow + 64] = av1.y;
        As[acol + 2][arow + 64] = av1.z;  As[acol + 3][arow + 64] = av1.w;
        *reinterpret_cast<float4*>(&Bs[brow][bcol])     = bv0;
        *reinterpret_cast<float4*>(&Bs[brow + 8][bcol]) = bv1;
        __syncthreads();

#pragma unroll
        for (int k = 0; k < 16; k++) {
            float4 a0 = *reinterpret_cast<const float4*>(&As[k][ty * 4]);
            float4 a1 = *reinterpret_cast<const float4*>(&As[k][ty * 4 + 64]);
            float4 b0 = *reinterpret_cast<const float4*>(&Bs[k][tx * 4]);
            float4 b1 = *reinterpret_cast<const float4*>(&Bs[k][tx * 4 + 64]);

            unsigned long long bb[4];
            bb[0] = pk2(b0.x, b0.y);  bb[1] = pk2(b0.z, b0.w);
            bb[2] = pk2(b1.x, b1.y);  bb[3] = pk2(b1.z, b1.w);

            float am[8] = {a0.x, a0.y, a0.z, a0.w, a1.x, a1.y, a1.z, a1.w};
#pragma unroll
            for (int i = 0; i < 8; i++) {
                unsigned long long ad = pk2(am[i], am[i]);
#pragma unroll
                for (int j = 0; j < 4; j++) fma2(acc[i][j], ad, bb[j]);
            }
        }
    }

    // ---- epilogue: tanh(acc + ws) . v -> per-row partial, reduce over tx ----
    const int b = m0 >> 11;              // T = 2048, BM=128 divides T
    const float* wsrow = g_ws + b * AA + n0;

    float wsv[8], vv[8];
#pragma unroll
    for (int jj = 0; jj < 8; jj++) {
        // columns: jj<4 -> tx*4+jj ; jj>=4 -> tx*4+64+(jj-4)
        const int col = (jj < 4) ? (tx * 4 + jj) : (tx * 4 + 60 + jj);
        wsv[jj] = wsrow[col];
        vv[jj]  = v[n0 + col];
    }

#pragma unroll
    for (int i = 0; i < 8; i++) {
        float ssum = 0.f;
#pragma unroll
        for (int j2 = 0; j2 < 4; j2++) {
            float lo, hi;
            up2(acc[i][j2], lo, hi);
            ssum += vv[2 * j2 + 0] * tanhf(lo + wsv[2 * j2 + 0]);
            ssum += vv[2 * j2 + 1] * tanhf(hi + wsv[2 * j2 + 1]);
        }
        // reduce across the 16 tx lanes (lane = (ty&1)*16 + tx; xor<=8 stays in group)
#pragma unroll
        for (int off = 8; off > 0; off >>= 1)
            ssum += __shfl_xor_sync(0xffffffffu, ssum, off);

        if (tx == 0) {
            const int row = (i < 4) ? (ty * 4 + i) : (ty * 4 + 60 + i);
            g_part[nb * MTOT + m0 + row] = ssum;   // single writer per slot
        }
    }
}

// ---------------------------------------------------------------------------
// Kernel 2: scores = sum over 8 partials; e = exp(scores) (raw, per reference);
//           g_invden[b] = 1/sum_t e.   grid 32, block 256
// ---------------------------------------------------------------------------
__global__ void softmax_kernel() {
    const int b = blockIdx.x;
    __shared__ float red[256];

    float local = 0.f;
    for (int t = threadIdx.x; t < TT; t += 256) {
        const int m = b * TT + t;
        float sc = 0.f;
#pragma unroll
        for (int p = 0; p < 8; p++) sc += g_part[p * MTOT + m];
        const float e = expf(sc);
        g_esc[m] = e;
        local += e;
    }
    red[threadIdx.x] = local;
    __syncthreads();
    for (int s = 128; s > 0; s >>= 1) {
        if (threadIdx.x < s) red[threadIdx.x] += red[threadIdx.x + s];
        __syncthreads();
    }
    if (threadIdx.x == 0) g_invden[b] = 1.0f / red[0];
}

// ---------------------------------------------------------------------------
// Kernel 3: c[b][d] = (sum_t e[b][t] * h[b][t][d]) * invden[b]
// grid (4, 32), block 256 — memory-bound, one full coalesced pass over h.
// ---------------------------------------------------------------------------
__global__ void ctx_kernel(const float* __restrict__ h, float* __restrict__ out) {
    const int b = blockIdx.y;
    const int d = blockIdx.x * 256 + threadIdx.x;
    __shared__ float w[128];

    const float* hb = h + (size_t)b * TT * DD;
    float acc0 = 0.f, acc1 = 0.f;

    for (int t0 = 0; t0 < TT; t0 += 128) {
        __syncthreads();
        if (threadIdx.x < 128) w[threadIdx.x] = g_esc[b * TT + t0 + threadIdx.x];
        __syncthreads();
#pragma unroll 16
        for (int i = 0; i < 128; i += 2) {
            acc0 += w[i + 0] * hb[(size_t)(t0 + i + 0) * DD + d];
            acc1 += w[i + 1] * hb[(size_t)(t0 + i + 1) * DD + d];
        }
    }
    out[b * DD + d] = (acc0 + acc1) * g_invden[b];
}

// ---------------------------------------------------------------------------
// Launch (graph-capturable: kernels only, default stream, no allocs/syncs)
// Inputs per metadata order: s, h, W_a, U_a, v_a (all float32)
// ---------------------------------------------------------------------------
extern "C" void kernel_launch(void* const* d_in, const int* in_sizes, int n_in,
                              void* d_out, int out_size) {
    const float* s  = (const float*)d_in[0];
    const float* h  = (const float*)d_in[1];
    const float* Wa = (const float*)d_in[2];
    const float* Ua = (const float*)d_in[3];
    const float* va = (const float*)d_in[4];
    float* out = (float*)d_out;

    ws_kernel       <<<dim3(8, 32),  128>>>(s, Wa);
    score_gemm_kernel<<<dim3(8, 512), 256>>>(h, Ua, va);
    softmax_kernel  <<<32,           256>>>();
    ctx_kernel      <<<dim3(4, 32),  256>>>(h, out);
}

// round 8
// speedup vs baseline: 1.0023x; 1.0023x over previous
#include <cuda_runtime.h>
#include <math.h>

// Problem constants (fixed by the dataset)
#define BB   32
#define TT   2048
#define DD   1024
#define AA   1024
#define MTOT (BB * TT)   // 65536 rows of the big GEMM

// ---------------------------------------------------------------------------
// Scratch (static __device__ arrays: allocation-free, graph-capture safe)
// ---------------------------------------------------------------------------
__device__ float g_ws[BB * AA];        // W_a_s : [B, A]
__device__ float g_part[8 * MTOT];     // per-(n-block) score partials, deterministic
__device__ float g_esc[MTOT];          // exp(scores)
__device__ float g_invden[BB];         // 1 / sum_t exp(scores)

// ---------------------------------------------------------------------------
// Packed fp32x2 helpers (Blackwell FFMA2 — only reachable via PTX)
// ---------------------------------------------------------------------------
__device__ __forceinline__ unsigned long long pk2(float lo, float hi) {
    unsigned long long r;
    asm("mov.b64 %0, {%1, %2};" : "=l"(r) : "f"(lo), "f"(hi));
    return r;
}
__device__ __forceinline__ void up2(unsigned long long v, float& lo, float& hi) {
    asm("mov.b64 {%0, %1}, %2;" : "=f"(lo), "=f"(hi) : "l"(v));
}
__device__ __forceinline__ void fma2(unsigned long long& d,
                                     unsigned long long a,
                                     unsigned long long b) {
    asm("fma.rn.f32x2 %0, %1, %2, %3;" : "=l"(d) : "l"(a), "l"(b), "l"(d));
}

// ---------------------------------------------------------------------------
// Kernel 0: g_ws[b][a] = sum_d s[b][d] * W_a[d][a]   (tiny GEMM, 67 MFLOP)
// grid (8, 32), block 128
// ---------------------------------------------------------------------------
__global__ void ws_kernel(const float* __restrict__ s, const float* __restrict__ W) {
    __shared__ float ss[DD];
    const int b = blockIdx.y;
    const int a = blockIdx.x * 128 + threadIdx.x;

    for (int i = threadIdx.x; i < DD; i += 128) ss[i] = s[b * DD + i];
    __syncthreads();

    float a0 = 0.f, a1 = 0.f, a2 = 0.f, a3 = 0.f;
    for (int d = 0; d < DD; d += 4) {
        a0 += ss[d + 0] * W[(size_t)(d + 0) * AA + a];
        a1 += ss[d + 1] * W[(size_t)(d + 1) * AA + a];
        a2 += ss[d + 2] * W[(size_t)(d + 2) * AA + a];
        a3 += ss[d + 3] * W[(size_t)(d + 3) * AA + a];
    }
    g_ws[b * AA + a] = (a0 + a1) + (a2 + a3);
}

// ---------------------------------------------------------------------------
// Kernel 1: fused GEMM + tanh + dot(v) -> per-n-block score partials.
//
// Tile: BM=128 x BN=128 x BK=16, 256 threads, 8x8 micro-tile per thread,
// accumulated in f32x2 pairs via fma.rn.f32x2 (2 FMAs per issue slot).
// Each block owns rows [m0, m0+128) (all inside one batch b since 128 | T)
// and columns [n0, n0+128). After the K loop it collapses its tile through
// tanh(acc + ws)·v into one partial per row and writes g_part[nb][m]
// (exactly one writer per slot -> deterministic, no atomics, no zero-init).
//
// grid (8, 512), block 256
// ---------------------------------------------------------------------------
__global__ void __launch_bounds__(256, 2)
score_gemm_kernel(const float* __restrict__ h,
                  const float* __restrict__ U,
                  const float* __restrict__ v) {
    __shared__ __align__(16) float As[16][132];   // [k][m], padded: STS 2-way max
    __shared__ __align__(16) float Bs[16][128];   // [k][n]

    const int tid = threadIdx.x;
    const int nb  = blockIdx.x;          // 0..7
    const int n0  = nb * 128;
    const int m0  = blockIdx.y * 128;

    // global->shared load mapping
    const int arow = tid >> 2;           // 0..63
    const int acol = (tid & 3) << 2;     // 0,4,8,12
    const int brow = tid >> 5;           // 0..7
    const int bcol = (tid & 31) << 2;    // 0..124

    // compute mapping: 16x16 thread grid, 8x8 micro-tile (4+4 split)
    const int ty = tid >> 4;             // 0..15 -> M
    const int tx = tid & 15;             // 0..15 -> N

    const float* hA = h + (size_t)m0 * DD;

    unsigned long long acc[8][4];
#pragma unroll
    for (int i = 0; i < 8; i++)
#pragma unroll
        for (int j = 0; j < 4; j++) acc[i][j] = 0ull;

    for (int kt = 0; kt < DD; kt += 16) {
        // issue global loads first (latency overlapped with prior compute)
        float4 av0 = *reinterpret_cast<const float4*>(&hA[(size_t)arow        * DD + kt + acol]);
        float4 av1 = *reinterpret_cast<const float4*>(&hA[(size_t)(arow + 64) * DD + kt + acol]);
        float4 bv0 = *reinterpret_cast<const float4*>(&U[(size_t)(kt + brow)     * AA + n0 + bcol]);
        float4 bv1 = *reinterpret_cast<const float4*>(&U[(size_t)(kt + brow + 8) * AA + n0 + bcol]);

        __syncthreads();   // previous tile fully consumed
        As[acol + 0][arow] = av0.x;  As[acol + 1][arow] = av0.y;
        As[acol + 2][arow] = av0.z;  As[acol + 3][arow] = av0.w;
        As[acol + 0][arow + 64] = av1.x;  As[acol + 1][arow + 64] = av1.y;
        As[acol + 2][arow + 64] = av1.z;  As[acol + 3][arow + 64] = av1.w;
        *reinterpret_cast<float4*>(&Bs[brow][bcol])     = bv0;
        *reinterpret_cast<float4*>(&Bs[brow + 8][bcol]) = bv1;
        __syncthreads();

#pragma unroll
        for (int k = 0; k < 16; k++) {
            float4 a0 = *reinterpret_cast<const float4*>(&As[k][ty * 4]);
            float4 a1 = *reinterpret_cast<const float4*>(&As[k][ty * 4 + 64]);
            float4 b0 = *reinterpret_cast<const float4*>(&Bs[k][tx * 4]);
            float4 b1 = *reinterpret_cast<const float4*>(&Bs[k][tx * 4 + 64]);

            unsigned long long bb[4];
            bb[0] = pk2(b0.x, b0.y);  bb[1] = pk2(b0.z, b0.w);
            bb[2] = pk2(b1.x, b1.y);  bb[3] = pk2(b1.z, b1.w);

            float am[8] = {a0.x, a0.y, a0.z, a0.w, a1.x, a1.y, a1.z, a1.w};
#pragma unroll
            for (int i = 0; i < 8; i++) {
                unsigned long long ad = pk2(am[i], am[i]);
#pragma unroll
                for (int j = 0; j < 4; j++) fma2(acc[i][j], ad, bb[j]);
            }
        }
    }

    // ---- epilogue: tanh(acc + ws) . v -> per-row partial, reduce over tx ----
    const int b = m0 >> 11;              // T = 2048, BM=128 divides T
    const float* wsrow = g_ws + b * AA + n0;

    float wsv[8], vv[8];
#pragma unroll
    for (int jj = 0; jj < 8; jj++) {
        // columns: jj<4 -> tx*4+jj ; jj>=4 -> tx*4+64+(jj-4)
        const int col = (jj < 4) ? (tx * 4 + jj) : (tx * 4 + 60 + jj);
        wsv[jj] = wsrow[col];
        vv[jj]  = v[n0 + col];
    }

#pragma unroll
    for (int i = 0; i < 8; i++) {
        float ssum = 0.f;
#pragma unroll
        for (int j2 = 0; j2 < 4; j2++) {
            float lo, hi;
            up2(acc[i][j2], lo, hi);
            ssum += vv[2 * j2 + 0] * tanhf(lo + wsv[2 * j2 + 0]);
            ssum += vv[2 * j2 + 1] * tanhf(hi + wsv[2 * j2 + 1]);
        }
        // reduce across the 16 tx lanes (lane = (ty&1)*16 + tx; xor<=8 stays in group)
#pragma unroll
        for (int off = 8; off > 0; off >>= 1)
            ssum += __shfl_xor_sync(0xffffffffu, ssum, off);

        if (tx == 0) {
            const int row = (i < 4) ? (ty * 4 + i) : (ty * 4 + 60 + i);
            g_part[nb * MTOT + m0 + row] = ssum;   // single writer per slot
        }
    }
}

// ---------------------------------------------------------------------------
// Kernel 2: scores = sum over 8 partials; e = exp(scores) (raw, per reference);
//           g_invden[b] = 1/sum_t e.   grid 32, block 256
// ---------------------------------------------------------------------------
__global__ void softmax_kernel() {
    const int b = blockIdx.x;
    __shared__ float red[256];

    float local = 0.f;
    for (int t = threadIdx.x; t < TT; t += 256) {
        const int m = b * TT + t;
        float sc = 0.f;
#pragma unroll
        for (int p = 0; p < 8; p++) sc += g_part[p * MTOT + m];
        const float e = expf(sc);
        g_esc[m] = e;
        local += e;
    }
    red[threadIdx.x] = local;
    __syncthreads();
    for (int s = 128; s > 0; s >>= 1) {
        if (threadIdx.x < s) red[threadIdx.x] += red[threadIdx.x + s];
        __syncthreads();
    }
    if (threadIdx.x == 0) g_invden[b] = 1.0f / red[0];
}

// ---------------------------------------------------------------------------
// Kernel 3: c[b][d] = (sum_t e[b][t] * h[b][t][d]) * invden[b]
// grid (4, 32), block 256 — memory-bound, one full coalesced pass over h.
// ---------------------------------------------------------------------------
__global__ void ctx_kernel(const float* __restrict__ h, float* __restrict__ out) {
    const int b = blockIdx.y;
    const int d = blockIdx.x * 256 + threadIdx.x;
    __shared__ float w[128];

    const float* hb = h + (size_t)b * TT * DD;
    float acc0 = 0.f, acc1 = 0.f;

    for (int t0 = 0; t0 < TT; t0 += 128) {
        __syncthreads();
        if (threadIdx.x < 128) w[threadIdx.x] = g_esc[b * TT + t0 + threadIdx.x];
        __syncthreads();
#pragma unroll 16
        for (int i = 0; i < 128; i += 2) {
            acc0 += w[i + 0] * hb[(size_t)(t0 + i + 0) * DD + d];
            acc1 += w[i + 1] * hb[(size_t)(t0 + i + 1) * DD + d];
        }
    }
    out[b * DD + d] = (acc0 + acc1) * g_invden[b];
}

// ---------------------------------------------------------------------------
// Launch (graph-capturable: kernels only, default stream, no allocs/syncs)
// Inputs per metadata order: s, h, W_a, U_a, v_a (all float32)
// ---------------------------------------------------------------------------
extern "C" void kernel_launch(void* const* d_in, const int* in_sizes, int n_in,
                              void* d_out, int out_size) {
    const float* s  = (const float*)d_in[0];
    const float* h  = (const float*)d_in[1];
    const float* Wa = (const float*)d_in[2];
    const float* Ua = (const float*)d_in[3];
    const float* va = (const float*)d_in[4];
    float* out = (float*)d_out;

    ws_kernel       <<<dim3(8, 32),  128>>>(s, Wa);
    score_gemm_kernel<<<dim3(8, 512), 256>>>(h, Ua, va);
    softmax_kernel  <<<32,           256>>>();
    ctx_kernel      <<<dim3(4, 32),  256>>>(h, out);
}